// round 13
// baseline (speedup 1.0000x reference)
#include <cuda_runtime.h>
#include <cuda_bf16.h>
#include <math.h>
#include <stdint.h>

// Problem constants
#define B  64
#define L  2048
#define H  1024
#define V  32000
#define P  128
#define H2 2048          // 2*H
#define KO 1152          // H + P

#define CHUNKS 32        // L-splits for attention
#define LC (L / CHUNKS)  // 64
#define PS (H + 4)       // partial stride (16B aligned)

typedef unsigned long long U64;

union U64F2 { U64 u; float2 f; };

__device__ __forceinline__ U64 fma2(U64 a, U64 b, U64 c) {
    U64 d;
    asm("fma.rn.f32x2 %0, %1, %2, %3;" : "=l"(d) : "l"(a), "l"(b), "l"(c));
    return d;
}
__device__ __forceinline__ U64 mul2(U64 a, U64 b) {
    U64 d;
    asm("mul.rn.f32x2 %0, %1, %2;" : "=l"(d) : "l"(a), "l"(b));
    return d;
}
__device__ __forceinline__ float hsum2(U64 a) {
    U64F2 t; t.u = a; return t.f.x + t.f.y;
}
__device__ __forceinline__ U64 dup2(float x) {
    U64F2 t; t.f.x = x; t.f.y = x; return t.u;
}
__device__ __forceinline__ U64 pack2(float x, float y) {
    U64F2 t; t.f.x = x; t.f.y = y; return t.u;
}
// pack two floats to half2: lo = x (even k), hi = y
__device__ __forceinline__ uint32_t f2h2(float x, float y) {
    uint32_t r;
    asm("cvt.rn.f16x2.f32 %0, %1, %2;" : "=r"(r) : "f"(y), "f"(x));
    return r;
}
__device__ __forceinline__ uint32_t smem_u32(const void* p) {
    uint32_t a;
    asm("{ .reg .u64 t; cvta.to.shared.u64 t, %1; cvt.u32.u64 %0, t; }"
        : "=r"(a) : "l"(p));
    return a;
}

#define CP_ASYNC16(dst, src) \
    asm volatile("cp.async.cg.shared.global [%0], [%1], 16;" \
                 :: "r"(dst), "l"(src) : "memory")
#define CP_COMMIT  asm volatile("cp.async.commit_group;" ::: "memory")
#define CP_WAIT_1  asm volatile("cp.async.wait_group 1;" ::: "memory")
#define CP_WAIT_0  asm volatile("cp.async.wait_group 0;" ::: "memory")

// Scratch (device globals — no allocation allowed)
__device__ float g_hnew[B * H];
__device__ float g_cat[B * H2];                 // [h_new | context]
__device__ float g_catp[B * KO];                // [concat_out | prior]
__device__ float g_energy[B * L];
__device__ float g_part[B * CHUNKS * PS];       // ctx partial + (m, s)
__device__ float g_pih[4 * B * 3 * H];          // GRU ih partials (ksplit=4)
__device__ float g_phh[4 * B * 3 * H];          // GRU hh partials
__device__ float g_pcc[16 * B * H];             // concat partials (ksplit=16)

// ---------------------------------------------------------------------------
// SIMT GEMM (GRU + concat): C[b,n] = sum_k A[b,k]*W[n,k]
// Optional row indirection for A0 (embedding gather folded in).
// ---------------------------------------------------------------------------
#define GKT 32

__global__ void __launch_bounds__(256)
gemm_kernel(const float* __restrict__ A0, const float* __restrict__ A1,
            const float* __restrict__ W0, const float* __restrict__ W1,
            float* __restrict__ C0, float* __restrict__ C1,
            const float* __restrict__ bias,
            int N, int K, int ksplit, int ldc,
            const int* __restrict__ gidx)     // if non-null: A0 rows = A0 + gidx[r]*K
{
    __shared__ U64 As2[16][66];
    __shared__ U64 Ws2[16][130];

    const float* A = blockIdx.z ? A1 : A0;
    const float* W = blockIdx.z ? W1 : W0;
    float*       C = blockIdx.z ? C1 : C0;
    bool use_g = (gidx != nullptr) && (blockIdx.z == 0);

    int vbase = blockIdx.x * 128;
    int kc    = K / ksplit;
    int k0    = blockIdx.y * kc;
    int tiles = kc / GKT;

    int tid = threadIdx.x;
    int vg  = tid >> 4;
    int bg  = tid & 15;
    int r8  = tid >> 3;
    int k4  = tid & 7;

    const float* arow[2];
    #pragma unroll
    for (int i = 0; i < 2; i++) {
        int r = r8 + i * 32;
        size_t ro = use_g ? (size_t)__ldg(&gidx[r]) : (size_t)r;
        arow[i] = A + ro * K;
    }

    U64 acc[8][4];
    #pragma unroll
    for (int v = 0; v < 8; v++)
        #pragma unroll
        for (int j = 0; j < 4; j++) acc[v][j] = 0ull;

    float4 pa[2], pw[4];
    {
        int kt = k0 + k4 * 4;
        #pragma unroll
        for (int i = 0; i < 2; i++)
            pa[i] = *(const float4*)(arow[i] + kt);
        #pragma unroll
        for (int i = 0; i < 4; i++)
            pw[i] = *(const float4*)(W + (size_t)(vbase + r8 + i * 32) * K + kt);
    }

    for (int t = 0; t < tiles; t++) {
        __syncthreads();
        #pragma unroll
        for (int i = 0; i < 2; i++) {
            int b = r8 + i * 32;
            As2[2 * k4][b]     = pack2(pa[i].x, pa[i].y);
            As2[2 * k4 + 1][b] = pack2(pa[i].z, pa[i].w);
        }
        #pragma unroll
        for (int i = 0; i < 4; i++) {
            int n = r8 + i * 32;
            Ws2[2 * k4][n]     = pack2(pw[i].x, pw[i].y);
            Ws2[2 * k4 + 1][n] = pack2(pw[i].z, pw[i].w);
        }
        __syncthreads();

        if (t + 1 < tiles) {
            int kt = k0 + (t + 1) * GKT + k4 * 4;
            #pragma unroll
            for (int i = 0; i < 2; i++)
                pa[i] = *(const float4*)(arow[i] + kt);
            #pragma unroll
            for (int i = 0; i < 4; i++)
                pw[i] = *(const float4*)(W + (size_t)(vbase + r8 + i * 32) * K + kt);
        }

        #pragma unroll
        for (int kp = 0; kp < 16; kp++) {
            ulonglong2 a01 = *(const ulonglong2*)&As2[kp][bg * 4];
            ulonglong2 a23 = *(const ulonglong2*)&As2[kp][bg * 4 + 2];
            ulonglong2 w01 = *(const ulonglong2*)&Ws2[kp][vg * 8];
            ulonglong2 w23 = *(const ulonglong2*)&Ws2[kp][vg * 8 + 2];
            ulonglong2 w45 = *(const ulonglong2*)&Ws2[kp][vg * 8 + 4];
            ulonglong2 w67 = *(const ulonglong2*)&Ws2[kp][vg * 8 + 6];
            U64 a[4] = {a01.x, a01.y, a23.x, a23.y};
            U64 w[8] = {w01.x, w01.y, w23.x, w23.y, w45.x, w45.y, w67.x, w67.y};
            #pragma unroll
            for (int v = 0; v < 8; v++) {
                acc[v][0] = fma2(a[0], w[v], acc[v][0]);
                acc[v][1] = fma2(a[1], w[v], acc[v][1]);
                acc[v][2] = fma2(a[2], w[v], acc[v][2]);
                acc[v][3] = fma2(a[3], w[v], acc[v][3]);
            }
        }
    }

    float bv[8];
    #pragma unroll
    for (int v = 0; v < 8; v++)
        bv[v] = bias ? bias[vbase + vg * 8 + v] : 0.0f;

    float* Cb = bias ? C : (C + (size_t)blockIdx.y * 64 * ldc);
    #pragma unroll
    for (int j = 0; j < 4; j++) {
        int b = bg * 4 + j;
        float4 o0, o1;
        o0.x = hsum2(acc[0][j]) + bv[0];
        o0.y = hsum2(acc[1][j]) + bv[1];
        o0.z = hsum2(acc[2][j]) + bv[2];
        o0.w = hsum2(acc[3][j]) + bv[3];
        o1.x = hsum2(acc[4][j]) + bv[4];
        o1.y = hsum2(acc[5][j]) + bv[5];
        o1.z = hsum2(acc[6][j]) + bv[6];
        o1.w = hsum2(acc[7][j]) + bv[7];
        float* cp = Cb + (size_t)b * ldc + vbase + vg * 8;
        *(float4*)cp       = o0;
        *(float4*)(cp + 4) = o1;
    }
}

// ---------------------------------------------------------------------------
// GRU gates
// ---------------------------------------------------------------------------
__global__ void gru_gates_kernel(const float* __restrict__ lh,
                                 const float* __restrict__ bih,
                                 const float* __restrict__ bhh,
                                 float* __restrict__ out_h)
{
    int idx = blockIdx.x * 256 + threadIdx.x;
    int b = idx >> 10;
    int c = idx & 1023;

    float gir = 0.f, giz = 0.f, gin = 0.f, ghr = 0.f, ghz = 0.f, ghn = 0.f;
    #pragma unroll
    for (int s = 0; s < 4; s++) {
        size_t base = ((size_t)(s * 64 + b)) * (3 * H) + c;
        gir += g_pih[base];
        giz += g_pih[base + H];
        gin += g_pih[base + 2 * H];
        ghr += g_phh[base];
        ghz += g_phh[base + H];
        ghn += g_phh[base + 2 * H];
    }
    gir += bih[c]; giz += bih[c + H]; gin += bih[c + 2 * H];
    ghr += bhh[c]; ghz += bhh[c + H]; ghn += bhh[c + 2 * H];

    float r = 1.0f / (1.0f + expf(-(gir + ghr)));
    float z = 1.0f / (1.0f + expf(-(giz + ghz)));
    float n = tanhf(gin + r * ghn);
    float hp = lh[(size_t)b * H + c];
    float hn = (1.0f - z) * n + z * hp;

    g_hnew[(size_t)b * H + c] = hn;
    g_cat[(size_t)b * H2 + c] = hn;
    if (out_h) out_h[(size_t)b * H + c] = hn;
}

// ---------------------------------------------------------------------------
// concat reduce
// ---------------------------------------------------------------------------
__global__ void creduce_kernel(const float* __restrict__ bc)
{
    int idx = blockIdx.x * 256 + threadIdx.x;
    int b = idx >> 10;
    int c = idx & 1023;
    float s = 0.f;
    #pragma unroll
    for (int k = 0; k < 16; k++)
        s += g_pcc[((size_t)(k * 64 + b)) * H + c];
    g_catp[(size_t)b * KO + c] = tanhf(s + bc[c]);
}

// ---------------------------------------------------------------------------
// Attention pass 1: cp.async 2-stage pipelined flash attention.
// One warp per (b, chunk); CHUNKS=32 -> LC=64 rows per warp (32 pair-iters).
// ---------------------------------------------------------------------------
extern __shared__ float attn_smem[];   // 4 warps * 2 stages * 2 rows * H floats

__global__ void __launch_bounds__(128)
attn1_kernel(const float* __restrict__ enc)
{
    int warp = threadIdx.x >> 5;
    int lane = threadIdx.x & 31;
    int gw   = blockIdx.x * 4 + warp;
    int b    = gw >> 5;    // / CHUNKS
    int ch   = gw & 31;    // % CHUNKS
    int l0   = ch * LC;

    uint32_t wbase = smem_u32(attn_smem) + warp * 16384u;
    float*   wptr  = attn_smem + warp * 4096;

    U64 q[16];
    {
        const float* qp = g_hnew + (size_t)b * H;
        #pragma unroll
        for (int j = 0; j < 8; j++) {
            ulonglong2 v = *(const ulonglong2*)(qp + j * 128 + lane * 4);
            q[2 * j] = v.x; q[2 * j + 1] = v.y;
        }
    }

    U64 cacc[16];
    #pragma unroll
    for (int i = 0; i < 16; i++) cacc[i] = 0ull;
    float m = -1e30f, s = 0.0f;

    {
        const float* eg0 = enc + ((size_t)l0 * B + b) * H + lane * 4;
        uint32_t d0 = wbase + lane * 16u;
        #pragma unroll
        for (int j = 0; j < 8; j++) {
            CP_ASYNC16(d0 + j * 512u,          eg0 + j * 128);
            CP_ASYNC16(d0 + 4096u + j * 512u,  eg0 + (size_t)B * H + j * 128);
        }
        CP_COMMIT;
    }

    #pragma unroll 1
    for (int i = 0; i < LC / 2; i++) {
        int stage = i & 1;

        if (i + 1 < LC / 2) {
            const float* eg0 = enc + ((size_t)(l0 + 2 * (i + 1)) * B + b) * H + lane * 4;
            uint32_t d0 = wbase + (uint32_t)((stage ^ 1) * 8192) + lane * 16u;
            #pragma unroll
            for (int j = 0; j < 8; j++) {
                CP_ASYNC16(d0 + j * 512u,          eg0 + j * 128);
                CP_ASYNC16(d0 + 4096u + j * 512u,  eg0 + (size_t)B * H + j * 128);
            }
            CP_COMMIT;
            CP_WAIT_1;
        } else {
            CP_WAIT_0;
        }

        const float* sb = wptr + stage * 2048 + lane * 4;
        U64 ev0[16], ev1[16];
        #pragma unroll
        for (int j = 0; j < 8; j++) {
            ulonglong2 v0 = *(const ulonglong2*)(sb + j * 128);
            ulonglong2 v1 = *(const ulonglong2*)(sb + 1024 + j * 128);
            ev0[2 * j] = v0.x; ev0[2 * j + 1] = v0.y;
            ev1[2 * j] = v1.x; ev1[2 * j + 1] = v1.y;
        }

        U64 ea0 = 0ull, ea1 = 0ull;
        #pragma unroll
        for (int k = 0; k < 16; k++) {
            ea0 = fma2(ev0[k], q[k], ea0);
            ea1 = fma2(ev1[k], q[k], ea1);
        }
        float e0 = hsum2(ea0);
        float e1 = hsum2(ea1);
        #pragma unroll
        for (int off = 16; off > 0; off >>= 1) {
            e0 += __shfl_xor_sync(0xffffffffu, e0, off);
            e1 += __shfl_xor_sync(0xffffffffu, e1, off);
        }

        if (lane == 0) {
            g_energy[(size_t)b * L + l0 + 2 * i]     = e0;
            g_energy[(size_t)b * L + l0 + 2 * i + 1] = e1;
        }

        float mn = fmaxf(m, fmaxf(e0, e1));
        float sc = expf(m - mn);
        float p0 = expf(e0 - mn);
        float p1 = expf(e1 - mn);
        s = s * sc + p0 + p1;
        m = mn;
        U64 sc2 = dup2(sc), pp0 = dup2(p0), pp1 = dup2(p1);
        #pragma unroll
        for (int k = 0; k < 16; k++) {
            U64 t = mul2(cacc[k], sc2);
            t = fma2(ev0[k], pp0, t);
            cacc[k] = fma2(ev1[k], pp1, t);
        }
    }

    float* pb = g_part + (size_t)(b * CHUNKS + ch) * PS;
    #pragma unroll
    for (int j = 0; j < 8; j++) {
        ulonglong2 w;
        w.x = cacc[2 * j]; w.y = cacc[2 * j + 1];
        *(ulonglong2*)(pb + j * 128 + lane * 4) = w;
    }
    if (lane == 0) { pb[H] = m; pb[H + 1] = s; }
}

// ---------------------------------------------------------------------------
// Combine partials — MLP-oriented (R12, known good).
// ---------------------------------------------------------------------------
__global__ void __launch_bounds__(256)
combine_kernel(const float* __restrict__ prior,
               float* __restrict__ out, int write_attn)
{
    int b  = blockIdx.x;
    int sl = blockIdx.y;
    int t  = threadIdx.x;
    int c4 = t & 63;
    int g  = t >> 6;

    __shared__ float  shm[CHUNKS], shs[CHUNKS], shw[CHUNKS];
    __shared__ float  shM, shS;
    __shared__ float4 red[4][64];

    if (t < CHUNKS) {
        shm[t] = g_part[(size_t)(b * CHUNKS + t) * PS + H];
        shs[t] = g_part[(size_t)(b * CHUNKS + t) * PS + H + 1];
    }
    __syncthreads();
    if (t < 32) {
        float M = shm[t];
        #pragma unroll
        for (int off = 16; off > 0; off >>= 1)
            M = fmaxf(M, __shfl_xor_sync(0xffffffffu, M, off));
        float w = expf(shm[t] - M);
        float S = shs[t] * w;
        #pragma unroll
        for (int off = 16; off > 0; off >>= 1)
            S += __shfl_xor_sync(0xffffffffu, S, off);
        shw[t] = w;
        if (t == 0) { shM = M; shS = S; }
    }
    __syncthreads();
    float M = shM;
    float invS = 1.0f / shS;

    {
        int h = sl * 256 + c4 * 4;
        const float* pp = g_part + (size_t)b * CHUNKS * PS + h;
        float4 acc = make_float4(0.f, 0.f, 0.f, 0.f);
        #pragma unroll
        for (int i = 0; i < 8; i++) {
            int ci = g * 8 + i;
            float4 v = *(const float4*)(pp + (size_t)ci * PS);
            float w = shw[ci];
            acc.x += w * v.x; acc.y += w * v.y;
            acc.z += w * v.z; acc.w += w * v.w;
        }
        red[g][c4] = acc;
    }
    __syncthreads();

    if (t < 64) {
        float4 a0 = red[0][t], a1 = red[1][t], a2 = red[2][t], a3 = red[3][t];
        float4 o;
        o.x = (a0.x + a1.x + a2.x + a3.x) * invS;
        o.y = (a0.y + a1.y + a2.y + a3.y) * invS;
        o.z = (a0.z + a1.z + a2.z + a3.z) * invS;
        o.w = (a0.w + a1.w + a2.w + a3.w) * invS;
        *(float4*)(g_cat + (size_t)b * H2 + H + sl * 256 + t * 4) = o;
    }

    if (write_attn) {
        size_t base = (size_t)B * V + (size_t)B * H + (size_t)b * L;
        int l0 = sl * (L / 4);
        for (int l = l0 + t; l < l0 + L / 4; l += 256)
            out[base + l] = expf(g_energy[(size_t)b * L + l] - M) * invS;
    }

    if (sl == 0 && t < P)
        g_catp[(size_t)b * KO + H + t] = prior[(size_t)b * P + t];
}

// ---------------------------------------------------------------------------
// Output GEMM via mma.sync fp16 (m16n8k16) with cp.async 3-stage pipeline.
// Block = 128v x 64b, 8 warps (2x4), warp tile 64m x 16n. K-tiles of 32.
// fp32 staged gmem->smem by cp.async; cvt to half2 at fragment-load time.
// Copy for tile t+2 issued at iter t -> 2 MMA phases in flight.
// ---------------------------------------------------------------------------
#define OKT 32
#define OTILES (KO / OKT)   // 36
#define FSTRIDE 36          // floats per staged row (32 data + 4 pad)
#define A_SZ (128 * FSTRIDE)
#define B_SZ (64 * FSTRIDE)
#define STG_SZ (A_SZ + B_SZ)
#define OG_SMEM_BYTES (3 * STG_SZ * 4)   // 82944 B

__device__ __forceinline__ void mma_f16(float* d, uint32_t a0, uint32_t a1,
                                        uint32_t a2, uint32_t a3,
                                        uint32_t b0, uint32_t b1)
{
    asm volatile(
        "mma.sync.aligned.m16n8k16.row.col.f32.f16.f16.f32 "
        "{%0,%1,%2,%3}, {%4,%5,%6,%7}, {%8,%9}, {%0,%1,%2,%3};"
        : "+f"(d[0]), "+f"(d[1]), "+f"(d[2]), "+f"(d[3])
        : "r"(a0), "r"(a1), "r"(a2), "r"(a3), "r"(b0), "r"(b1));
}

extern __shared__ float og_smem[];

__global__ void __launch_bounds__(256)
out_gemm_tc_kernel(const float* __restrict__ Wout,
                   const float* __restrict__ bout,
                   float* __restrict__ outp)
{
    uint32_t sbase = smem_u32(og_smem);

    int tid   = threadIdx.x;
    int wid   = tid >> 5;
    int lane  = tid & 31;
    int gid   = lane >> 2;
    int tig   = lane & 3;
    int vbase = blockIdx.x * 128;

    int warp_m = wid & 1;
    int warp_n = wid >> 1;
    int mbase  = warp_m * 64;
    int nbase  = warp_n * 16;

    // copy indexing: A 4 x 16B chunks/thread, B 2 x 16B chunks/thread
    int a_row = tid >> 1;   // 0..127
    int a_h   = tid & 1;    // chunk col16 = a_h*4 + j
    int b_row = tid >> 2;   // 0..63
    int b_q   = tid & 3;    // chunk col16 = b_q*2 + j  (b_q in 0..3, 8 chunks/row)

    const float* Asrc0 = Wout + (size_t)(vbase + a_row) * KO;
    const float* Bsrc0 = g_catp + (size_t)b_row * KO;
    uint32_t Adst0 = sbase + (uint32_t)(a_row * FSTRIDE) * 4u;
    uint32_t Bdst0 = sbase + (uint32_t)(A_SZ + b_row * FSTRIDE) * 4u;

    float acc[4][2][4];
    #pragma unroll
    for (int mt = 0; mt < 4; mt++)
        #pragma unroll
        for (int nt = 0; nt < 2; nt++)
            #pragma unroll
            for (int i = 0; i < 4; i++) acc[mt][nt][i] = 0.0f;

    // issue copy for tile t into stage stg
    #define OG_ISSUE(t, stg) do {                                            \
        uint32_t so = (uint32_t)(stg) * (STG_SZ * 4u);                        \
        const float* as = Asrc0 + (t) * OKT;                                  \
        const float* bs = Bsrc0 + (t) * OKT;                                  \
        _Pragma("unroll")                                                     \
        for (int j = 0; j < 4; j++)                                           \
            CP_ASYNC16(Adst0 + so + (uint32_t)(a_h * 4 + j) * 16u,            \
                       as + (a_h * 4 + j) * 4);                               \
        _Pragma("unroll")                                                     \
        for (int j = 0; j < 2; j++)                                           \
            CP_ASYNC16(Bdst0 + so + (uint32_t)(b_q * 2 + j) * 16u,            \
                       bs + (b_q * 2 + j) * 4);                               \
        CP_COMMIT;                                                            \
    } while (0)

    OG_ISSUE(0, 0);
    OG_ISSUE(1, 1);

    int stg = 0;
    #pragma unroll 1
    for (int t = 0; t < OTILES; t++) {
        if (t + 1 < OTILES) { CP_WAIT_1; } else { CP_WAIT_0; }
        __syncthreads();   // tile t data visible; all warps done with stage being refilled

        if (t + 2 < OTILES) {
            int ns = stg + 2; if (ns >= 3) ns -= 3;
            OG_ISSUE(t + 2, ns);
        }

        const float* As = og_smem + stg * STG_SZ;
        const float* Bs = As + A_SZ;

        #pragma unroll
        for (int kb = 0; kb < 2; kb++) {
            int kc = kb * 16 + 2 * tig;   // fp32 column of this thread's k-pair

            uint32_t bf0[2], bf1[2];
            #pragma unroll
            for (int nt = 0; nt < 2; nt++) {
                int n0 = nbase + nt * 8 + gid;
                float2 v0 = *(const float2*)&Bs[n0 * FSTRIDE + kc];
                float2 v1 = *(const float2*)&Bs[n0 * FSTRIDE + kc + 8];
                bf0[nt] = f2h2(v0.x, v0.y);
                bf1[nt] = f2h2(v1.x, v1.y);
            }
            #pragma unroll
            for (int mt = 0; mt < 4; mt++) {
                int r0 = mbase + mt * 16 + gid;
                float2 x0 = *(const float2*)&As[r0 * FSTRIDE + kc];
                float2 x1 = *(const float2*)&As[(r0 + 8) * FSTRIDE + kc];
                float2 x2 = *(const float2*)&As[r0 * FSTRIDE + kc + 8];
                float2 x3 = *(const float2*)&As[(r0 + 8) * FSTRIDE + kc + 8];
                uint32_t a0 = f2h2(x0.x, x0.y);
                uint32_t a1 = f2h2(x1.x, x1.y);
                uint32_t a2 = f2h2(x2.x, x2.y);
                uint32_t a3 = f2h2(x3.x, x3.y);
                mma_f16(acc[mt][0], a0, a1, a2, a3, bf0[0], bf1[0]);
                mma_f16(acc[mt][1], a0, a1, a2, a3, bf0[1], bf1[1]);
            }
        }

        stg++; if (stg >= 3) stg = 0;
    }

    // epilogue: D[v, b] -> outp[b*V + v] + bias[v]
    #pragma unroll
    for (int mt = 0; mt < 4; mt++) {
        int v0 = vbase + mbase + mt * 16 + gid;
        float bias0 = bout[v0];
        float bias1 = bout[v0 + 8];
        #pragma unroll
        for (int nt = 0; nt < 2; nt++) {
            int bcol = nbase + nt * 8 + 2 * tig;
            outp[(size_t)bcol * V + v0]           = acc[mt][nt][0] + bias0;
            outp[(size_t)(bcol + 1) * V + v0]     = acc[mt][nt][1] + bias0;
            outp[(size_t)bcol * V + v0 + 8]       = acc[mt][nt][2] + bias1;
            outp[(size_t)(bcol + 1) * V + v0 + 8] = acc[mt][nt][3] + bias1;
        }
    }
}

// ---------------------------------------------------------------------------
extern "C" void kernel_launch(void* const* d_in, const int* in_sizes, int n_in,
                              void* d_out, int out_size)
{
    const int*   seq   = (const int*)d_in[0];   // int32 (JAX x64 disabled)
    const float* lh    = (const float*)d_in[1];
    const float* enc   = (const float*)d_in[2];
    const float* prior = (const float*)d_in[3];
    const float* emb   = (const float*)d_in[4];
    const float* Wih   = (const float*)d_in[5];
    const float* Whh   = (const float*)d_in[6];
    const float* bih   = (const float*)d_in[7];
    const float* bhh   = (const float*)d_in[8];
    const float* Wc    = (const float*)d_in[9];
    const float* bc    = (const float*)d_in[10];
    const float* Wout  = (const float*)d_in[11];
    const float* bout  = (const float*)d_in[12];

    float* out = (float*)d_out;
    long long need_h    = (long long)B * V + (long long)B * H;
    long long need_attn = need_h + (long long)B * L;
    float* out_h = ((long long)out_size >= need_h) ? out + (size_t)B * V : nullptr;
    int write_attn = ((long long)out_size >= need_attn) ? 1 : 0;

    float* pih; cudaGetSymbolAddress((void**)&pih, g_pih);
    float* phh; cudaGetSymbolAddress((void**)&phh, g_phh);
    float* pcc; cudaGetSymbolAddress((void**)&pcc, g_pcc);
    float* gcat; cudaGetSymbolAddress((void**)&gcat, g_cat);

    cudaFuncSetAttribute(attn1_kernel,
                         cudaFuncAttributeMaxDynamicSharedMemorySize, 65536);
    cudaFuncSetAttribute(out_gemm_tc_kernel,
                         cudaFuncAttributeMaxDynamicSharedMemorySize, OG_SMEM_BYTES);

    // 1. GRU GEMMs: gi = emb[seq]@Wih^T (gather folded in), gh = h@Whh^T
    gemm_kernel<<<dim3(3 * H / 128, 4, 2), 256>>>(
        emb, lh, Wih, Whh, pih, phh, nullptr, 3 * H, H, 4, 3 * H, seq);

    // 2. gates -> h_new
    gru_gates_kernel<<<B * H / 256, 256>>>(lh, bih, bhh, out_h);

    // 3. flash attention over encoder_outputs (read once, 2-stage cp.async)
    attn1_kernel<<<B * CHUNKS / 4, 128, 65536>>>(enc);

    // 4. combine -> context, attn weights, prior copy
    combine_kernel<<<dim3(B, 4), 256>>>(prior, out, write_attn);

    // 5. concat GEMM (N=1024, K=2048, ksplit=16) + reduce/tanh
    gemm_kernel<<<dim3(H / 128, 16, 1), 256>>>(
        gcat, gcat, Wc, Wc, pcc, pcc, nullptr, H, H2, 16, H, nullptr);
    creduce_kernel<<<B * H / 256, 256>>>(bc);

    // 6. output GEMM (N=32000, K=1152) via mma.sync fp16 + cp.async pipeline
    out_gemm_tc_kernel<<<V / 128, 256, OG_SMEM_BYTES>>>(Wout, bout, out);
}

// round 14
// speedup vs baseline: 1.2342x; 1.2342x over previous
#include <cuda_runtime.h>
#include <cuda_bf16.h>
#include <math.h>
#include <stdint.h>

// Problem constants
#define B  64
#define L  2048
#define H  1024
#define V  32000
#define P  128
#define H2 2048          // 2*H
#define KO 1152          // H + P

#define CHUNKS 32        // L-splits for attention
#define LC (L / CHUNKS)  // 64
#define PS (H + 4)       // partial stride (16B aligned)

typedef unsigned long long U64;

union U64F2 { U64 u; float2 f; };

__device__ __forceinline__ U64 fma2(U64 a, U64 b, U64 c) {
    U64 d;
    asm("fma.rn.f32x2 %0, %1, %2, %3;" : "=l"(d) : "l"(a), "l"(b), "l"(c));
    return d;
}
__device__ __forceinline__ U64 mul2(U64 a, U64 b) {
    U64 d;
    asm("mul.rn.f32x2 %0, %1, %2;" : "=l"(d) : "l"(a), "l"(b));
    return d;
}
__device__ __forceinline__ float hsum2(U64 a) {
    U64F2 t; t.u = a; return t.f.x + t.f.y;
}
__device__ __forceinline__ U64 dup2(float x) {
    U64F2 t; t.f.x = x; t.f.y = x; return t.u;
}
__device__ __forceinline__ U64 pack2(float x, float y) {
    U64F2 t; t.f.x = x; t.f.y = y; return t.u;
}
// pack two floats to half2: lo = x (even k), hi = y
__device__ __forceinline__ uint32_t f2h2(float x, float y) {
    uint32_t r;
    asm("cvt.rn.f16x2.f32 %0, %1, %2;" : "=r"(r) : "f"(y), "f"(x));
    return r;
}
__device__ __forceinline__ uint32_t smem_u32(const void* p) {
    uint32_t a;
    asm("{ .reg .u64 t; cvta.to.shared.u64 t, %1; cvt.u32.u64 %0, t; }"
        : "=r"(a) : "l"(p));
    return a;
}

#define CP_ASYNC16(dst, src) \
    asm volatile("cp.async.cg.shared.global [%0], [%1], 16;" \
                 :: "r"(dst), "l"(src) : "memory")
#define CP_COMMIT  asm volatile("cp.async.commit_group;" ::: "memory")
#define CP_WAIT_1  asm volatile("cp.async.wait_group 1;" ::: "memory")
#define CP_WAIT_0  asm volatile("cp.async.wait_group 0;" ::: "memory")

// Scratch (device globals — no allocation allowed)
__device__ float g_hnew[B * H];
__device__ float g_cat[B * H2];                 // [h_new | context]
__device__ float g_catp[B * KO];                // [concat_out | prior]
__device__ float g_energy[B * L];
__device__ float g_part[B * CHUNKS * PS];       // ctx partial + (m, s)
__device__ float g_pih[4 * B * 3 * H];          // GRU ih partials (ksplit=4)
__device__ float g_phh[4 * B * 3 * H];          // GRU hh partials
__device__ float g_pcc[16 * B * H];             // concat partials (ksplit=16)

// ---------------------------------------------------------------------------
// SIMT GEMM (GRU): C[b,n] = sum_k A[b,k]*W[n,k]
// Optional row indirection for A0 (embedding gather folded in).
// ---------------------------------------------------------------------------
#define GKT 32

__global__ void __launch_bounds__(256)
gemm_kernel(const float* __restrict__ A0, const float* __restrict__ A1,
            const float* __restrict__ W0, const float* __restrict__ W1,
            float* __restrict__ C0, float* __restrict__ C1,
            const float* __restrict__ bias,
            int N, int K, int ksplit, int ldc,
            const int* __restrict__ gidx)     // if non-null: A0 rows = A0 + gidx[r]*K
{
    __shared__ U64 As2[16][66];
    __shared__ U64 Ws2[16][130];

    const float* A = blockIdx.z ? A1 : A0;
    const float* W = blockIdx.z ? W1 : W0;
    float*       C = blockIdx.z ? C1 : C0;
    bool use_g = (gidx != nullptr) && (blockIdx.z == 0);

    int vbase = blockIdx.x * 128;
    int kc    = K / ksplit;
    int k0    = blockIdx.y * kc;
    int tiles = kc / GKT;

    int tid = threadIdx.x;
    int vg  = tid >> 4;
    int bg  = tid & 15;
    int r8  = tid >> 3;
    int k4  = tid & 7;

    const float* arow[2];
    #pragma unroll
    for (int i = 0; i < 2; i++) {
        int r = r8 + i * 32;
        size_t ro = use_g ? (size_t)__ldg(&gidx[r]) : (size_t)r;
        arow[i] = A + ro * K;
    }

    U64 acc[8][4];
    #pragma unroll
    for (int v = 0; v < 8; v++)
        #pragma unroll
        for (int j = 0; j < 4; j++) acc[v][j] = 0ull;

    float4 pa[2], pw[4];
    {
        int kt = k0 + k4 * 4;
        #pragma unroll
        for (int i = 0; i < 2; i++)
            pa[i] = *(const float4*)(arow[i] + kt);
        #pragma unroll
        for (int i = 0; i < 4; i++)
            pw[i] = *(const float4*)(W + (size_t)(vbase + r8 + i * 32) * K + kt);
    }

    for (int t = 0; t < tiles; t++) {
        __syncthreads();
        #pragma unroll
        for (int i = 0; i < 2; i++) {
            int b = r8 + i * 32;
            As2[2 * k4][b]     = pack2(pa[i].x, pa[i].y);
            As2[2 * k4 + 1][b] = pack2(pa[i].z, pa[i].w);
        }
        #pragma unroll
        for (int i = 0; i < 4; i++) {
            int n = r8 + i * 32;
            Ws2[2 * k4][n]     = pack2(pw[i].x, pw[i].y);
            Ws2[2 * k4 + 1][n] = pack2(pw[i].z, pw[i].w);
        }
        __syncthreads();

        if (t + 1 < tiles) {
            int kt = k0 + (t + 1) * GKT + k4 * 4;
            #pragma unroll
            for (int i = 0; i < 2; i++)
                pa[i] = *(const float4*)(arow[i] + kt);
            #pragma unroll
            for (int i = 0; i < 4; i++)
                pw[i] = *(const float4*)(W + (size_t)(vbase + r8 + i * 32) * K + kt);
        }

        #pragma unroll
        for (int kp = 0; kp < 16; kp++) {
            ulonglong2 a01 = *(const ulonglong2*)&As2[kp][bg * 4];
            ulonglong2 a23 = *(const ulonglong2*)&As2[kp][bg * 4 + 2];
            ulonglong2 w01 = *(const ulonglong2*)&Ws2[kp][vg * 8];
            ulonglong2 w23 = *(const ulonglong2*)&Ws2[kp][vg * 8 + 2];
            ulonglong2 w45 = *(const ulonglong2*)&Ws2[kp][vg * 8 + 4];
            ulonglong2 w67 = *(const ulonglong2*)&Ws2[kp][vg * 8 + 6];
            U64 a[4] = {a01.x, a01.y, a23.x, a23.y};
            U64 w[8] = {w01.x, w01.y, w23.x, w23.y, w45.x, w45.y, w67.x, w67.y};
            #pragma unroll
            for (int v = 0; v < 8; v++) {
                acc[v][0] = fma2(a[0], w[v], acc[v][0]);
                acc[v][1] = fma2(a[1], w[v], acc[v][1]);
                acc[v][2] = fma2(a[2], w[v], acc[v][2]);
                acc[v][3] = fma2(a[3], w[v], acc[v][3]);
            }
        }
    }

    float bv[8];
    #pragma unroll
    for (int v = 0; v < 8; v++)
        bv[v] = bias ? bias[vbase + vg * 8 + v] : 0.0f;

    float* Cb = bias ? C : (C + (size_t)blockIdx.y * 64 * ldc);
    #pragma unroll
    for (int j = 0; j < 4; j++) {
        int b = bg * 4 + j;
        float4 o0, o1;
        o0.x = hsum2(acc[0][j]) + bv[0];
        o0.y = hsum2(acc[1][j]) + bv[1];
        o0.z = hsum2(acc[2][j]) + bv[2];
        o0.w = hsum2(acc[3][j]) + bv[3];
        o1.x = hsum2(acc[4][j]) + bv[4];
        o1.y = hsum2(acc[5][j]) + bv[5];
        o1.z = hsum2(acc[6][j]) + bv[6];
        o1.w = hsum2(acc[7][j]) + bv[7];
        float* cp = Cb + (size_t)b * ldc + vbase + vg * 8;
        *(float4*)cp       = o0;
        *(float4*)(cp + 4) = o1;
    }
}

// ---------------------------------------------------------------------------
// GRU gates
// ---------------------------------------------------------------------------
__global__ void gru_gates_kernel(const float* __restrict__ lh,
                                 const float* __restrict__ bih,
                                 const float* __restrict__ bhh,
                                 float* __restrict__ out_h)
{
    int idx = blockIdx.x * 256 + threadIdx.x;
    int b = idx >> 10;
    int c = idx & 1023;

    float gir = 0.f, giz = 0.f, gin = 0.f, ghr = 0.f, ghz = 0.f, ghn = 0.f;
    #pragma unroll
    for (int s = 0; s < 4; s++) {
        size_t base = ((size_t)(s * 64 + b)) * (3 * H) + c;
        gir += g_pih[base];
        giz += g_pih[base + H];
        gin += g_pih[base + 2 * H];
        ghr += g_phh[base];
        ghz += g_phh[base + H];
        ghn += g_phh[base + 2 * H];
    }
    gir += bih[c]; giz += bih[c + H]; gin += bih[c + 2 * H];
    ghr += bhh[c]; ghz += bhh[c + H]; ghn += bhh[c + 2 * H];

    float r = 1.0f / (1.0f + expf(-(gir + ghr)));
    float z = 1.0f / (1.0f + expf(-(giz + ghz)));
    float n = tanhf(gin + r * ghn);
    float hp = lh[(size_t)b * H + c];
    float hn = (1.0f - z) * n + z * hp;

    g_hnew[(size_t)b * H + c] = hn;
    g_cat[(size_t)b * H2 + c] = hn;
    if (out_h) out_h[(size_t)b * H + c] = hn;
}

// ---------------------------------------------------------------------------
// concat reduce
// ---------------------------------------------------------------------------
__global__ void creduce_kernel(const float* __restrict__ bc)
{
    int idx = blockIdx.x * 256 + threadIdx.x;
    int b = idx >> 10;
    int c = idx & 1023;
    float s = 0.f;
    #pragma unroll
    for (int k = 0; k < 16; k++)
        s += g_pcc[((size_t)(k * 64 + b)) * H + c];
    g_catp[(size_t)b * KO + c] = tanhf(s + bc[c]);
}

// ---------------------------------------------------------------------------
// Attention pass 1: cp.async 2-stage pipelined flash attention.
// ---------------------------------------------------------------------------
extern __shared__ float attn_smem[];   // 4 warps * 2 stages * 2 rows * H floats

__global__ void __launch_bounds__(128)
attn1_kernel(const float* __restrict__ enc)
{
    int warp = threadIdx.x >> 5;
    int lane = threadIdx.x & 31;
    int gw   = blockIdx.x * 4 + warp;
    int b    = gw >> 5;    // / CHUNKS
    int ch   = gw & 31;    // % CHUNKS
    int l0   = ch * LC;

    uint32_t wbase = smem_u32(attn_smem) + warp * 16384u;
    float*   wptr  = attn_smem + warp * 4096;

    U64 q[16];
    {
        const float* qp = g_hnew + (size_t)b * H;
        #pragma unroll
        for (int j = 0; j < 8; j++) {
            ulonglong2 v = *(const ulonglong2*)(qp + j * 128 + lane * 4);
            q[2 * j] = v.x; q[2 * j + 1] = v.y;
        }
    }

    U64 cacc[16];
    #pragma unroll
    for (int i = 0; i < 16; i++) cacc[i] = 0ull;
    float m = -1e30f, s = 0.0f;

    {
        const float* eg0 = enc + ((size_t)l0 * B + b) * H + lane * 4;
        uint32_t d0 = wbase + lane * 16u;
        #pragma unroll
        for (int j = 0; j < 8; j++) {
            CP_ASYNC16(d0 + j * 512u,          eg0 + j * 128);
            CP_ASYNC16(d0 + 4096u + j * 512u,  eg0 + (size_t)B * H + j * 128);
        }
        CP_COMMIT;
    }

    #pragma unroll 1
    for (int i = 0; i < LC / 2; i++) {
        int stage = i & 1;

        if (i + 1 < LC / 2) {
            const float* eg0 = enc + ((size_t)(l0 + 2 * (i + 1)) * B + b) * H + lane * 4;
            uint32_t d0 = wbase + (uint32_t)((stage ^ 1) * 8192) + lane * 16u;
            #pragma unroll
            for (int j = 0; j < 8; j++) {
                CP_ASYNC16(d0 + j * 512u,          eg0 + j * 128);
                CP_ASYNC16(d0 + 4096u + j * 512u,  eg0 + (size_t)B * H + j * 128);
            }
            CP_COMMIT;
            CP_WAIT_1;
        } else {
            CP_WAIT_0;
        }

        const float* sb = wptr + stage * 2048 + lane * 4;
        U64 ev0[16], ev1[16];
        #pragma unroll
        for (int j = 0; j < 8; j++) {
            ulonglong2 v0 = *(const ulonglong2*)(sb + j * 128);
            ulonglong2 v1 = *(const ulonglong2*)(sb + 1024 + j * 128);
            ev0[2 * j] = v0.x; ev0[2 * j + 1] = v0.y;
            ev1[2 * j] = v1.x; ev1[2 * j + 1] = v1.y;
        }

        U64 ea0 = 0ull, ea1 = 0ull;
        #pragma unroll
        for (int k = 0; k < 16; k++) {
            ea0 = fma2(ev0[k], q[k], ea0);
            ea1 = fma2(ev1[k], q[k], ea1);
        }
        float e0 = hsum2(ea0);
        float e1 = hsum2(ea1);
        #pragma unroll
        for (int off = 16; off > 0; off >>= 1) {
            e0 += __shfl_xor_sync(0xffffffffu, e0, off);
            e1 += __shfl_xor_sync(0xffffffffu, e1, off);
        }

        if (lane == 0) {
            g_energy[(size_t)b * L + l0 + 2 * i]     = e0;
            g_energy[(size_t)b * L + l0 + 2 * i + 1] = e1;
        }

        float mn = fmaxf(m, fmaxf(e0, e1));
        float sc = expf(m - mn);
        float p0 = expf(e0 - mn);
        float p1 = expf(e1 - mn);
        s = s * sc + p0 + p1;
        m = mn;
        U64 sc2 = dup2(sc), pp0 = dup2(p0), pp1 = dup2(p1);
        #pragma unroll
        for (int k = 0; k < 16; k++) {
            U64 t = mul2(cacc[k], sc2);
            t = fma2(ev0[k], pp0, t);
            cacc[k] = fma2(ev1[k], pp1, t);
        }
    }

    float* pb = g_part + (size_t)(b * CHUNKS + ch) * PS;
    #pragma unroll
    for (int j = 0; j < 8; j++) {
        ulonglong2 w;
        w.x = cacc[2 * j]; w.y = cacc[2 * j + 1];
        *(ulonglong2*)(pb + j * 128 + lane * 4) = w;
    }
    if (lane == 0) { pb[H] = m; pb[H + 1] = s; }
}

// ---------------------------------------------------------------------------
// Combine partials — MLP-oriented (R12, known good).
// ---------------------------------------------------------------------------
__global__ void __launch_bounds__(256)
combine_kernel(const float* __restrict__ prior,
               float* __restrict__ out, int write_attn)
{
    int b  = blockIdx.x;
    int sl = blockIdx.y;
    int t  = threadIdx.x;
    int c4 = t & 63;
    int g  = t >> 6;

    __shared__ float  shm[CHUNKS], shs[CHUNKS], shw[CHUNKS];
    __shared__ float  shM, shS;
    __shared__ float4 red[4][64];

    if (t < CHUNKS) {
        shm[t] = g_part[(size_t)(b * CHUNKS + t) * PS + H];
        shs[t] = g_part[(size_t)(b * CHUNKS + t) * PS + H + 1];
    }
    __syncthreads();
    if (t < 32) {
        float M = shm[t];
        #pragma unroll
        for (int off = 16; off > 0; off >>= 1)
            M = fmaxf(M, __shfl_xor_sync(0xffffffffu, M, off));
        float w = expf(shm[t] - M);
        float S = shs[t] * w;
        #pragma unroll
        for (int off = 16; off > 0; off >>= 1)
            S += __shfl_xor_sync(0xffffffffu, S, off);
        shw[t] = w;
        if (t == 0) { shM = M; shS = S; }
    }
    __syncthreads();
    float M = shM;
    float invS = 1.0f / shS;

    {
        int h = sl * 256 + c4 * 4;
        const float* pp = g_part + (size_t)b * CHUNKS * PS + h;
        float4 acc = make_float4(0.f, 0.f, 0.f, 0.f);
        #pragma unroll
        for (int i = 0; i < 8; i++) {
            int ci = g * 8 + i;
            float4 v = *(const float4*)(pp + (size_t)ci * PS);
            float w = shw[ci];
            acc.x += w * v.x; acc.y += w * v.y;
            acc.z += w * v.z; acc.w += w * v.w;
        }
        red[g][c4] = acc;
    }
    __syncthreads();

    if (t < 64) {
        float4 a0 = red[0][t], a1 = red[1][t], a2 = red[2][t], a3 = red[3][t];
        float4 o;
        o.x = (a0.x + a1.x + a2.x + a3.x) * invS;
        o.y = (a0.y + a1.y + a2.y + a3.y) * invS;
        o.z = (a0.z + a1.z + a2.z + a3.z) * invS;
        o.w = (a0.w + a1.w + a2.w + a3.w) * invS;
        *(float4*)(g_cat + (size_t)b * H2 + H + sl * 256 + t * 4) = o;
    }

    if (write_attn) {
        size_t base = (size_t)B * V + (size_t)B * H + (size_t)b * L;
        int l0 = sl * (L / 4);
        for (int l = l0 + t; l < l0 + L / 4; l += 256)
            out[base + l] = expf(g_energy[(size_t)b * L + l] - M) * invS;
    }

    if (sl == 0 && t < P)
        g_catp[(size_t)b * KO + H + t] = prior[(size_t)b * P + t];
}

// ---------------------------------------------------------------------------
// fp16 mma.sync GEMM core (m16n8k16): 128m x 64n tile, 8 warps (2x4),
// warp tile 64m x 16n, K-tiles of 32, double-buffered, one sync per tile.
// ---------------------------------------------------------------------------
#define OKT 32
#define HSTRIDE 20          // half2 per row

__device__ __forceinline__ void mma_f16(float* d, uint32_t a0, uint32_t a1,
                                        uint32_t a2, uint32_t a3,
                                        uint32_t b0, uint32_t b1)
{
    asm volatile(
        "mma.sync.aligned.m16n8k16.row.col.f32.f16.f16.f32 "
        "{%0,%1,%2,%3}, {%4,%5,%6,%7}, {%8,%9}, {%0,%1,%2,%3};"
        : "+f"(d[0]), "+f"(d[1]), "+f"(d[2]), "+f"(d[3])
        : "r"(a0), "r"(a1), "r"(a2), "r"(a3), "r"(b0), "r"(b1));
}

// Core loop shared by out_gemm and concat gemm (inlined via template-free macro
// style: implemented twice to keep addressing simple and registers tight).

// ---------------------------------------------------------------------------
// Output GEMM (R12 known-good): A=Wout [V x KO], B=g_catp [64 x KO], 36 tiles.
// ---------------------------------------------------------------------------
#define OTILES (KO / OKT)   // 36

__global__ void __launch_bounds__(256, 2)
out_gemm_tc_kernel(const float* __restrict__ Wout,
                   const float* __restrict__ bout,
                   float* __restrict__ outp)
{
    __shared__ uint32_t A_h[2][128 * HSTRIDE];
    __shared__ uint32_t B_h[2][64 * HSTRIDE];

    int tid   = threadIdx.x;
    int wid   = tid >> 5;
    int lane  = tid & 31;
    int gid   = lane >> 2;
    int tig   = lane & 3;
    int vbase = blockIdx.x * 128;

    int warp_m = wid & 1;
    int warp_n = wid >> 1;
    int mbase  = warp_m * 64;
    int nbase  = warp_n * 16;

    int arow = tid >> 3;
    int ac4  = tid & 7;

    float acc[4][2][4];
    #pragma unroll
    for (int mt = 0; mt < 4; mt++)
        #pragma unroll
        for (int nt = 0; nt < 2; nt++)
            #pragma unroll
            for (int i = 0; i < 4; i++) acc[mt][nt][i] = 0.0f;

    float4 pa[4], pb[2];

    #pragma unroll
    for (int j = 0; j < 4; j++) {
        int row = arow + j * 32;
        pa[j] = *(const float4*)(Wout + (size_t)(vbase + row) * KO + ac4 * 4);
    }
    #pragma unroll
    for (int j = 0; j < 2; j++) {
        int row = arow + j * 32;
        pb[j] = *(const float4*)(g_catp + (size_t)row * KO + ac4 * 4);
    }
    #pragma unroll
    for (int j = 0; j < 4; j++) {
        int row = arow + j * 32;
        *(uint2*)&A_h[0][row * HSTRIDE + ac4 * 2] =
            make_uint2(f2h2(pa[j].x, pa[j].y), f2h2(pa[j].z, pa[j].w));
    }
    #pragma unroll
    for (int j = 0; j < 2; j++) {
        int row = arow + j * 32;
        *(uint2*)&B_h[0][row * HSTRIDE + ac4 * 2] =
            make_uint2(f2h2(pb[j].x, pb[j].y), f2h2(pb[j].z, pb[j].w));
    }

    #pragma unroll 1
    for (int t = 0; t < OTILES; t++) {
        __syncthreads();
        int buf = t & 1;

        if (t + 1 < OTILES) {
            int kt = (t + 1) * OKT;
            #pragma unroll
            for (int j = 0; j < 4; j++) {
                int row = arow + j * 32;
                pa[j] = *(const float4*)(Wout + (size_t)(vbase + row) * KO + kt + ac4 * 4);
            }
            #pragma unroll
            for (int j = 0; j < 2; j++) {
                int row = arow + j * 32;
                pb[j] = *(const float4*)(g_catp + (size_t)row * KO + kt + ac4 * 4);
            }
        }

        #pragma unroll
        for (int kb = 0; kb < 2; kb++) {
            int k2 = kb * 8 + tig;

            uint32_t bf0[2], bf1[2];
            #pragma unroll
            for (int nt = 0; nt < 2; nt++) {
                int n0 = nbase + nt * 8 + gid;
                bf0[nt] = B_h[buf][n0 * HSTRIDE + k2];
                bf1[nt] = B_h[buf][n0 * HSTRIDE + k2 + 4];
            }
            #pragma unroll
            for (int mt = 0; mt < 4; mt++) {
                int r0 = mbase + mt * 16 + gid;
                uint32_t a0 = A_h[buf][r0 * HSTRIDE + k2];
                uint32_t a1 = A_h[buf][(r0 + 8) * HSTRIDE + k2];
                uint32_t a2 = A_h[buf][r0 * HSTRIDE + k2 + 4];
                uint32_t a3 = A_h[buf][(r0 + 8) * HSTRIDE + k2 + 4];
                mma_f16(acc[mt][0], a0, a1, a2, a3, bf0[0], bf1[0]);
                mma_f16(acc[mt][1], a0, a1, a2, a3, bf0[1], bf1[1]);
            }
        }

        if (t + 1 < OTILES) {
            int nbuf = buf ^ 1;
            #pragma unroll
            for (int j = 0; j < 4; j++) {
                int row = arow + j * 32;
                *(uint2*)&A_h[nbuf][row * HSTRIDE + ac4 * 2] =
                    make_uint2(f2h2(pa[j].x, pa[j].y), f2h2(pa[j].z, pa[j].w));
            }
            #pragma unroll
            for (int j = 0; j < 2; j++) {
                int row = arow + j * 32;
                *(uint2*)&B_h[nbuf][row * HSTRIDE + ac4 * 2] =
                    make_uint2(f2h2(pb[j].x, pb[j].y), f2h2(pb[j].z, pb[j].w));
            }
        }
    }

    #pragma unroll
    for (int mt = 0; mt < 4; mt++) {
        int v0 = vbase + mbase + mt * 16 + gid;
        float bias0 = bout[v0];
        float bias1 = bout[v0 + 8];
        #pragma unroll
        for (int nt = 0; nt < 2; nt++) {
            int bcol = nbase + nt * 8 + 2 * tig;
            outp[(size_t)bcol * V + v0]           = acc[mt][nt][0] + bias0;
            outp[(size_t)(bcol + 1) * V + v0]     = acc[mt][nt][1] + bias0;
            outp[(size_t)bcol * V + v0 + 8]       = acc[mt][nt][2] + bias1;
            outp[(size_t)(bcol + 1) * V + v0 + 8] = acc[mt][nt][3] + bias1;
        }
    }
}

// ---------------------------------------------------------------------------
// Concat GEMM via fp16 mma.sync: A=Wc [H x H2], B=g_cat [64 x H2].
// grid (H/128, 16): blockIdx.y = k-split (kc=128 -> 4 tiles of 32).
// Partials -> g_pcc[(split*64 + b)*H + n]; creduce applies sum+bias+tanh.
// Only feeds the logits path (h_new / attn_weights stay fp32-exact).
// ---------------------------------------------------------------------------
#define CTILES 4   // 128 / OKT

__global__ void __launch_bounds__(256, 2)
cgemm_tc_kernel(const float* __restrict__ Wc)
{
    __shared__ uint32_t A_h[2][128 * HSTRIDE];
    __shared__ uint32_t B_h[2][64 * HSTRIDE];

    int tid   = threadIdx.x;
    int wid   = tid >> 5;
    int lane  = tid & 31;
    int gid   = lane >> 2;
    int tig   = lane & 3;
    int vbase = blockIdx.x * 128;
    int k0    = blockIdx.y * 128;
    int yoff  = blockIdx.y * 64;

    int warp_m = wid & 1;
    int warp_n = wid >> 1;
    int mbase  = warp_m * 64;
    int nbase  = warp_n * 16;

    int arow = tid >> 3;
    int ac4  = tid & 7;

    float acc[4][2][4];
    #pragma unroll
    for (int mt = 0; mt < 4; mt++)
        #pragma unroll
        for (int nt = 0; nt < 2; nt++)
            #pragma unroll
            for (int i = 0; i < 4; i++) acc[mt][nt][i] = 0.0f;

    float4 pa[4], pb[2];

    #pragma unroll
    for (int j = 0; j < 4; j++) {
        int row = arow + j * 32;
        pa[j] = *(const float4*)(Wc + (size_t)(vbase + row) * H2 + k0 + ac4 * 4);
    }
    #pragma unroll
    for (int j = 0; j < 2; j++) {
        int row = arow + j * 32;
        pb[j] = *(const float4*)(g_cat + (size_t)row * H2 + k0 + ac4 * 4);
    }
    #pragma unroll
    for (int j = 0; j < 4; j++) {
        int row = arow + j * 32;
        *(uint2*)&A_h[0][row * HSTRIDE + ac4 * 2] =
            make_uint2(f2h2(pa[j].x, pa[j].y), f2h2(pa[j].z, pa[j].w));
    }
    #pragma unroll
    for (int j = 0; j < 2; j++) {
        int row = arow + j * 32;
        *(uint2*)&B_h[0][row * HSTRIDE + ac4 * 2] =
            make_uint2(f2h2(pb[j].x, pb[j].y), f2h2(pb[j].z, pb[j].w));
    }

    #pragma unroll 1
    for (int t = 0; t < CTILES; t++) {
        __syncthreads();
        int buf = t & 1;

        if (t + 1 < CTILES) {
            int kt = k0 + (t + 1) * OKT;
            #pragma unroll
            for (int j = 0; j < 4; j++) {
                int row = arow + j * 32;
                pa[j] = *(const float4*)(Wc + (size_t)(vbase + row) * H2 + kt + ac4 * 4);
            }
            #pragma unroll
            for (int j = 0; j < 2; j++) {
                int row = arow + j * 32;
                pb[j] = *(const float4*)(g_cat + (size_t)row * H2 + kt + ac4 * 4);
            }
        }

        #pragma unroll
        for (int kb = 0; kb < 2; kb++) {
            int k2 = kb * 8 + tig;

            uint32_t bf0[2], bf1[2];
            #pragma unroll
            for (int nt = 0; nt < 2; nt++) {
                int n0 = nbase + nt * 8 + gid;
                bf0[nt] = B_h[buf][n0 * HSTRIDE + k2];
                bf1[nt] = B_h[buf][n0 * HSTRIDE + k2 + 4];
            }
            #pragma unroll
            for (int mt = 0; mt < 4; mt++) {
                int r0 = mbase + mt * 16 + gid;
                uint32_t a0 = A_h[buf][r0 * HSTRIDE + k2];
                uint32_t a1 = A_h[buf][(r0 + 8) * HSTRIDE + k2];
                uint32_t a2 = A_h[buf][r0 * HSTRIDE + k2 + 4];
                uint32_t a3 = A_h[buf][(r0 + 8) * HSTRIDE + k2 + 4];
                mma_f16(acc[mt][0], a0, a1, a2, a3, bf0[0], bf1[0]);
                mma_f16(acc[mt][1], a0, a1, a2, a3, bf0[1], bf1[1]);
            }
        }

        if (t + 1 < CTILES) {
            int nbuf = buf ^ 1;
            #pragma unroll
            for (int j = 0; j < 4; j++) {
                int row = arow + j * 32;
                *(uint2*)&A_h[nbuf][row * HSTRIDE + ac4 * 2] =
                    make_uint2(f2h2(pa[j].x, pa[j].y), f2h2(pa[j].z, pa[j].w));
            }
            #pragma unroll
            for (int j = 0; j < 2; j++) {
                int row = arow + j * 32;
                *(uint2*)&B_h[nbuf][row * HSTRIDE + ac4 * 2] =
                    make_uint2(f2h2(pb[j].x, pb[j].y), f2h2(pb[j].z, pb[j].w));
            }
        }
    }

    // partial store: g_pcc[(yoff + b)*H + n]
    #pragma unroll
    for (int mt = 0; mt < 4; mt++) {
        int n0 = vbase + mbase + mt * 16 + gid;
        #pragma unroll
        for (int nt = 0; nt < 2; nt++) {
            int bcol = nbase + nt * 8 + 2 * tig;
            g_pcc[(size_t)(yoff + bcol) * H + n0]           = acc[mt][nt][0];
            g_pcc[(size_t)(yoff + bcol + 1) * H + n0]       = acc[mt][nt][1];
            g_pcc[(size_t)(yoff + bcol) * H + n0 + 8]       = acc[mt][nt][2];
            g_pcc[(size_t)(yoff + bcol + 1) * H + n0 + 8]   = acc[mt][nt][3];
        }
    }
}

// ---------------------------------------------------------------------------
extern "C" void kernel_launch(void* const* d_in, const int* in_sizes, int n_in,
                              void* d_out, int out_size)
{
    const int*   seq   = (const int*)d_in[0];   // int32 (JAX x64 disabled)
    const float* lh    = (const float*)d_in[1];
    const float* enc   = (const float*)d_in[2];
    const float* prior = (const float*)d_in[3];
    const float* emb   = (const float*)d_in[4];
    const float* Wih   = (const float*)d_in[5];
    const float* Whh   = (const float*)d_in[6];
    const float* bih   = (const float*)d_in[7];
    const float* bhh   = (const float*)d_in[8];
    const float* Wc    = (const float*)d_in[9];
    const float* bc    = (const float*)d_in[10];
    const float* Wout  = (const float*)d_in[11];
    const float* bout  = (const float*)d_in[12];

    float* out = (float*)d_out;
    long long need_h    = (long long)B * V + (long long)B * H;
    long long need_attn = need_h + (long long)B * L;
    float* out_h = ((long long)out_size >= need_h) ? out + (size_t)B * V : nullptr;
    int write_attn = ((long long)out_size >= need_attn) ? 1 : 0;

    float* pih; cudaGetSymbolAddress((void**)&pih, g_pih);
    float* phh; cudaGetSymbolAddress((void**)&phh, g_phh);

    cudaFuncSetAttribute(attn1_kernel,
                         cudaFuncAttributeMaxDynamicSharedMemorySize, 65536);

    // 1. GRU GEMMs (fp32 SIMT — h_new must stay exact):
    //    gi = emb[seq]@Wih^T (gather folded in), gh = h@Whh^T
    gemm_kernel<<<dim3(3 * H / 128, 4, 2), 256>>>(
        emb, lh, Wih, Whh, pih, phh, nullptr, 3 * H, H, 4, 3 * H, seq);

    // 2. gates -> h_new
    gru_gates_kernel<<<B * H / 256, 256>>>(lh, bih, bhh, out_h);

    // 3. flash attention over encoder_outputs (read once, 2-stage cp.async)
    attn1_kernel<<<B * CHUNKS / 4, 128, 65536>>>(enc);

    // 4. combine -> context, attn weights, prior copy
    combine_kernel<<<dim3(B, 4), 256>>>(prior, out, write_attn);

    // 5. concat GEMM via fp16 tensor cores (ksplit=16) + reduce/tanh
    cgemm_tc_kernel<<<dim3(H / 128, 16), 256>>>(Wc);
    creduce_kernel<<<B * H / 256, 256>>>(bc);

    // 6. output GEMM (N=32000, K=1152) via mma.sync fp16 (R12 config)
    out_gemm_tc_kernel<<<V / 128, 256>>>(Wout, bout, out);
}

// round 15
// speedup vs baseline: 1.2587x; 1.0198x over previous
#include <cuda_runtime.h>
#include <cuda_bf16.h>
#include <math.h>
#include <stdint.h>

// Problem constants
#define B  64
#define L  2048
#define H  1024
#define V  32000
#define P  128
#define H2 2048          // 2*H
#define KO 1152          // H + P

#define CHUNKS 32        // L-splits for attention
#define LC (L / CHUNKS)  // 64
#define PS (H + 4)       // partial stride (16B aligned)

#define KSPL 8           // GRU k-split

typedef unsigned long long U64;

union U64F2 { U64 u; float2 f; };

__device__ __forceinline__ U64 fma2(U64 a, U64 b, U64 c) {
    U64 d;
    asm("fma.rn.f32x2 %0, %1, %2, %3;" : "=l"(d) : "l"(a), "l"(b), "l"(c));
    return d;
}
__device__ __forceinline__ U64 mul2(U64 a, U64 b) {
    U64 d;
    asm("mul.rn.f32x2 %0, %1, %2;" : "=l"(d) : "l"(a), "l"(b));
    return d;
}
__device__ __forceinline__ float hsum2(U64 a) {
    U64F2 t; t.u = a; return t.f.x + t.f.y;
}
__device__ __forceinline__ U64 dup2(float x) {
    U64F2 t; t.f.x = x; t.f.y = x; return t.u;
}
__device__ __forceinline__ U64 pack2(float x, float y) {
    U64F2 t; t.f.x = x; t.f.y = y; return t.u;
}
// pack two floats to half2: lo = x (even k), hi = y
__device__ __forceinline__ uint32_t f2h2(float x, float y) {
    uint32_t r;
    asm("cvt.rn.f16x2.f32 %0, %1, %2;" : "=r"(r) : "f"(y), "f"(x));
    return r;
}
__device__ __forceinline__ uint32_t smem_u32(const void* p) {
    uint32_t a;
    asm("{ .reg .u64 t; cvta.to.shared.u64 t, %1; cvt.u32.u64 %0, t; }"
        : "=r"(a) : "l"(p));
    return a;
}

#define CP_ASYNC16(dst, src) \
    asm volatile("cp.async.cg.shared.global [%0], [%1], 16;" \
                 :: "r"(dst), "l"(src) : "memory")
#define CP_COMMIT  asm volatile("cp.async.commit_group;" ::: "memory")
#define CP_WAIT_1  asm volatile("cp.async.wait_group 1;" ::: "memory")
#define CP_WAIT_0  asm volatile("cp.async.wait_group 0;" ::: "memory")

// Scratch (device globals — no allocation allowed)
__device__ float g_hnew[B * H];
__device__ float g_cat[B * H2];                 // [h_new | context]
__device__ float g_catp[B * KO];                // [concat_out | prior]
__device__ float g_energy[B * L];
__device__ float g_part[B * CHUNKS * PS];       // ctx partial + (m, s)
__device__ float g_pih[KSPL * B * 3 * H];       // GRU ih partials
__device__ float g_phh[KSPL * B * 3 * H];       // GRU hh partials
__device__ float g_pcc[16 * B * H];             // concat partials (ksplit=16)

// ---------------------------------------------------------------------------
// SIMT GEMM (GRU): C[b,n] = sum_k A[b,k]*W[n,k]
// Optional row indirection for A0 (embedding gather folded in).
// ---------------------------------------------------------------------------
#define GKT 32

__global__ void __launch_bounds__(256)
gemm_kernel(const float* __restrict__ A0, const float* __restrict__ A1,
            const float* __restrict__ W0, const float* __restrict__ W1,
            float* __restrict__ C0, float* __restrict__ C1,
            const float* __restrict__ bias,
            int N, int K, int ksplit, int ldc,
            const int* __restrict__ gidx)     // if non-null: A0 rows = A0 + gidx[r]*K
{
    __shared__ U64 As2[16][66];
    __shared__ U64 Ws2[16][130];

    const float* A = blockIdx.z ? A1 : A0;
    const float* W = blockIdx.z ? W1 : W0;
    float*       C = blockIdx.z ? C1 : C0;
    bool use_g = (gidx != nullptr) && (blockIdx.z == 0);

    int vbase = blockIdx.x * 128;
    int kc    = K / ksplit;
    int k0    = blockIdx.y * kc;
    int tiles = kc / GKT;

    int tid = threadIdx.x;
    int vg  = tid >> 4;
    int bg  = tid & 15;
    int r8  = tid >> 3;
    int k4  = tid & 7;

    const float* arow[2];
    #pragma unroll
    for (int i = 0; i < 2; i++) {
        int r = r8 + i * 32;
        size_t ro = use_g ? (size_t)__ldg(&gidx[r]) : (size_t)r;
        arow[i] = A + ro * K;
    }

    U64 acc[8][4];
    #pragma unroll
    for (int v = 0; v < 8; v++)
        #pragma unroll
        for (int j = 0; j < 4; j++) acc[v][j] = 0ull;

    float4 pa[2], pw[4];
    {
        int kt = k0 + k4 * 4;
        #pragma unroll
        for (int i = 0; i < 2; i++)
            pa[i] = *(const float4*)(arow[i] + kt);
        #pragma unroll
        for (int i = 0; i < 4; i++)
            pw[i] = *(const float4*)(W + (size_t)(vbase + r8 + i * 32) * K + kt);
    }

    for (int t = 0; t < tiles; t++) {
        __syncthreads();
        #pragma unroll
        for (int i = 0; i < 2; i++) {
            int b = r8 + i * 32;
            As2[2 * k4][b]     = pack2(pa[i].x, pa[i].y);
            As2[2 * k4 + 1][b] = pack2(pa[i].z, pa[i].w);
        }
        #pragma unroll
        for (int i = 0; i < 4; i++) {
            int n = r8 + i * 32;
            Ws2[2 * k4][n]     = pack2(pw[i].x, pw[i].y);
            Ws2[2 * k4 + 1][n] = pack2(pw[i].z, pw[i].w);
        }
        __syncthreads();

        if (t + 1 < tiles) {
            int kt = k0 + (t + 1) * GKT + k4 * 4;
            #pragma unroll
            for (int i = 0; i < 2; i++)
                pa[i] = *(const float4*)(arow[i] + kt);
            #pragma unroll
            for (int i = 0; i < 4; i++)
                pw[i] = *(const float4*)(W + (size_t)(vbase + r8 + i * 32) * K + kt);
        }

        #pragma unroll
        for (int kp = 0; kp < 16; kp++) {
            ulonglong2 a01 = *(const ulonglong2*)&As2[kp][bg * 4];
            ulonglong2 a23 = *(const ulonglong2*)&As2[kp][bg * 4 + 2];
            ulonglong2 w01 = *(const ulonglong2*)&Ws2[kp][vg * 8];
            ulonglong2 w23 = *(const ulonglong2*)&Ws2[kp][vg * 8 + 2];
            ulonglong2 w45 = *(const ulonglong2*)&Ws2[kp][vg * 8 + 4];
            ulonglong2 w67 = *(const ulonglong2*)&Ws2[kp][vg * 8 + 6];
            U64 a[4] = {a01.x, a01.y, a23.x, a23.y};
            U64 w[8] = {w01.x, w01.y, w23.x, w23.y, w45.x, w45.y, w67.x, w67.y};
            #pragma unroll
            for (int v = 0; v < 8; v++) {
                acc[v][0] = fma2(a[0], w[v], acc[v][0]);
                acc[v][1] = fma2(a[1], w[v], acc[v][1]);
                acc[v][2] = fma2(a[2], w[v], acc[v][2]);
                acc[v][3] = fma2(a[3], w[v], acc[v][3]);
            }
        }
    }

    float bv[8];
    #pragma unroll
    for (int v = 0; v < 8; v++)
        bv[v] = bias ? bias[vbase + vg * 8 + v] : 0.0f;

    float* Cb = bias ? C : (C + (size_t)blockIdx.y * 64 * ldc);
    #pragma unroll
    for (int j = 0; j < 4; j++) {
        int b = bg * 4 + j;
        float4 o0, o1;
        o0.x = hsum2(acc[0][j]) + bv[0];
        o0.y = hsum2(acc[1][j]) + bv[1];
        o0.z = hsum2(acc[2][j]) + bv[2];
        o0.w = hsum2(acc[3][j]) + bv[3];
        o1.x = hsum2(acc[4][j]) + bv[4];
        o1.y = hsum2(acc[5][j]) + bv[5];
        o1.z = hsum2(acc[6][j]) + bv[6];
        o1.w = hsum2(acc[7][j]) + bv[7];
        float* cp = Cb + (size_t)b * ldc + vbase + vg * 8;
        *(float4*)cp       = o0;
        *(float4*)(cp + 4) = o1;
    }
}

// ---------------------------------------------------------------------------
// GRU gates — vectorized: thread handles 4 consecutive columns (float4).
// ---------------------------------------------------------------------------
__global__ void gru_gates_kernel(const float* __restrict__ lh,
                                 const float* __restrict__ bih,
                                 const float* __restrict__ bhh,
                                 float* __restrict__ out_h)
{
    int idx = blockIdx.x * 256 + threadIdx.x;   // 0..16383
    int b  = idx >> 8;          // /(H/4)
    int c  = (idx & 255) * 4;

    float4 gir = make_float4(0,0,0,0), giz = gir, gin = gir;
    float4 ghr = gir, ghz = gir, ghn = gir;
    #pragma unroll
    for (int s = 0; s < KSPL; s++) {
        size_t base = ((size_t)(s * 64 + b)) * (3 * H) + c;
        float4 v;
        v = *(const float4*)&g_pih[base];
        gir.x += v.x; gir.y += v.y; gir.z += v.z; gir.w += v.w;
        v = *(const float4*)&g_pih[base + H];
        giz.x += v.x; giz.y += v.y; giz.z += v.z; giz.w += v.w;
        v = *(const float4*)&g_pih[base + 2 * H];
        gin.x += v.x; gin.y += v.y; gin.z += v.z; gin.w += v.w;
        v = *(const float4*)&g_phh[base];
        ghr.x += v.x; ghr.y += v.y; ghr.z += v.z; ghr.w += v.w;
        v = *(const float4*)&g_phh[base + H];
        ghz.x += v.x; ghz.y += v.y; ghz.z += v.z; ghz.w += v.w;
        v = *(const float4*)&g_phh[base + 2 * H];
        ghn.x += v.x; ghn.y += v.y; ghn.z += v.z; ghn.w += v.w;
    }

    float4 bir = *(const float4*)&bih[c];
    float4 biz = *(const float4*)&bih[c + H];
    float4 bin = *(const float4*)&bih[c + 2 * H];
    float4 bhr = *(const float4*)&bhh[c];
    float4 bhz = *(const float4*)&bhh[c + H];
    float4 bhn = *(const float4*)&bhh[c + 2 * H];
    float4 hp  = *(const float4*)&lh[(size_t)b * H + c];

    float4 hn;
    {
        float r, z, n;
        r = 1.0f / (1.0f + expf(-(gir.x + bir.x + ghr.x + bhr.x)));
        z = 1.0f / (1.0f + expf(-(giz.x + biz.x + ghz.x + bhz.x)));
        n = tanhf(gin.x + bin.x + r * (ghn.x + bhn.x));
        hn.x = (1.0f - z) * n + z * hp.x;
        r = 1.0f / (1.0f + expf(-(gir.y + bir.y + ghr.y + bhr.y)));
        z = 1.0f / (1.0f + expf(-(giz.y + biz.y + ghz.y + bhz.y)));
        n = tanhf(gin.y + bin.y + r * (ghn.y + bhn.y));
        hn.y = (1.0f - z) * n + z * hp.y;
        r = 1.0f / (1.0f + expf(-(gir.z + bir.z + ghr.z + bhr.z)));
        z = 1.0f / (1.0f + expf(-(giz.z + biz.z + ghz.z + bhz.z)));
        n = tanhf(gin.z + bin.z + r * (ghn.z + bhn.z));
        hn.z = (1.0f - z) * n + z * hp.z;
        r = 1.0f / (1.0f + expf(-(gir.w + bir.w + ghr.w + bhr.w)));
        z = 1.0f / (1.0f + expf(-(giz.w + biz.w + ghz.w + bhz.w)));
        n = tanhf(gin.w + bin.w + r * (ghn.w + bhn.w));
        hn.w = (1.0f - z) * n + z * hp.w;
    }

    *(float4*)&g_hnew[(size_t)b * H + c] = hn;
    *(float4*)&g_cat[(size_t)b * H2 + c] = hn;
    if (out_h) *(float4*)&out_h[(size_t)b * H + c] = hn;
}

// ---------------------------------------------------------------------------
// concat reduce — vectorized: 4 columns per thread, 16 independent LDG.128.
// ---------------------------------------------------------------------------
__global__ void creduce_kernel(const float* __restrict__ bc)
{
    int idx = blockIdx.x * 256 + threadIdx.x;   // 0..16383
    int b = idx >> 8;
    int c = (idx & 255) * 4;
    float4 s = make_float4(0, 0, 0, 0);
    #pragma unroll
    for (int k = 0; k < 16; k++) {
        float4 v = *(const float4*)&g_pcc[((size_t)(k * 64 + b)) * H + c];
        s.x += v.x; s.y += v.y; s.z += v.z; s.w += v.w;
    }
    float4 bv = *(const float4*)&bc[c];
    float4 o;
    o.x = tanhf(s.x + bv.x);
    o.y = tanhf(s.y + bv.y);
    o.z = tanhf(s.z + bv.z);
    o.w = tanhf(s.w + bv.w);
    *(float4*)&g_catp[(size_t)b * KO + c] = o;
}

// ---------------------------------------------------------------------------
// Attention pass 1: cp.async 2-stage pipelined flash attention.
// ---------------------------------------------------------------------------
extern __shared__ float attn_smem[];   // 4 warps * 2 stages * 2 rows * H floats

__global__ void __launch_bounds__(128)
attn1_kernel(const float* __restrict__ enc)
{
    int warp = threadIdx.x >> 5;
    int lane = threadIdx.x & 31;
    int gw   = blockIdx.x * 4 + warp;
    int b    = gw >> 5;    // / CHUNKS
    int ch   = gw & 31;    // % CHUNKS
    int l0   = ch * LC;

    uint32_t wbase = smem_u32(attn_smem) + warp * 16384u;
    float*   wptr  = attn_smem + warp * 4096;

    U64 q[16];
    {
        const float* qp = g_hnew + (size_t)b * H;
        #pragma unroll
        for (int j = 0; j < 8; j++) {
            ulonglong2 v = *(const ulonglong2*)(qp + j * 128 + lane * 4);
            q[2 * j] = v.x; q[2 * j + 1] = v.y;
        }
    }

    U64 cacc[16];
    #pragma unroll
    for (int i = 0; i < 16; i++) cacc[i] = 0ull;
    float m = -1e30f, s = 0.0f;

    {
        const float* eg0 = enc + ((size_t)l0 * B + b) * H + lane * 4;
        uint32_t d0 = wbase + lane * 16u;
        #pragma unroll
        for (int j = 0; j < 8; j++) {
            CP_ASYNC16(d0 + j * 512u,          eg0 + j * 128);
            CP_ASYNC16(d0 + 4096u + j * 512u,  eg0 + (size_t)B * H + j * 128);
        }
        CP_COMMIT;
    }

    #pragma unroll 1
    for (int i = 0; i < LC / 2; i++) {
        int stage = i & 1;

        if (i + 1 < LC / 2) {
            const float* eg0 = enc + ((size_t)(l0 + 2 * (i + 1)) * B + b) * H + lane * 4;
            uint32_t d0 = wbase + (uint32_t)((stage ^ 1) * 8192) + lane * 16u;
            #pragma unroll
            for (int j = 0; j < 8; j++) {
                CP_ASYNC16(d0 + j * 512u,          eg0 + j * 128);
                CP_ASYNC16(d0 + 4096u + j * 512u,  eg0 + (size_t)B * H + j * 128);
            }
            CP_COMMIT;
            CP_WAIT_1;
        } else {
            CP_WAIT_0;
        }

        const float* sb = wptr + stage * 2048 + lane * 4;
        U64 ev0[16], ev1[16];
        #pragma unroll
        for (int j = 0; j < 8; j++) {
            ulonglong2 v0 = *(const ulonglong2*)(sb + j * 128);
            ulonglong2 v1 = *(const ulonglong2*)(sb + 1024 + j * 128);
            ev0[2 * j] = v0.x; ev0[2 * j + 1] = v0.y;
            ev1[2 * j] = v1.x; ev1[2 * j + 1] = v1.y;
        }

        U64 ea0 = 0ull, ea1 = 0ull;
        #pragma unroll
        for (int k = 0; k < 16; k++) {
            ea0 = fma2(ev0[k], q[k], ea0);
            ea1 = fma2(ev1[k], q[k], ea1);
        }
        float e0 = hsum2(ea0);
        float e1 = hsum2(ea1);
        #pragma unroll
        for (int off = 16; off > 0; off >>= 1) {
            e0 += __shfl_xor_sync(0xffffffffu, e0, off);
            e1 += __shfl_xor_sync(0xffffffffu, e1, off);
        }

        if (lane == 0) {
            g_energy[(size_t)b * L + l0 + 2 * i]     = e0;
            g_energy[(size_t)b * L + l0 + 2 * i + 1] = e1;
        }

        float mn = fmaxf(m, fmaxf(e0, e1));
        float sc = expf(m - mn);
        float p0 = expf(e0 - mn);
        float p1 = expf(e1 - mn);
        s = s * sc + p0 + p1;
        m = mn;
        U64 sc2 = dup2(sc), pp0 = dup2(p0), pp1 = dup2(p1);
        #pragma unroll
        for (int k = 0; k < 16; k++) {
            U64 t = mul2(cacc[k], sc2);
            t = fma2(ev0[k], pp0, t);
            cacc[k] = fma2(ev1[k], pp1, t);
        }
    }

    float* pb = g_part + (size_t)(b * CHUNKS + ch) * PS;
    #pragma unroll
    for (int j = 0; j < 8; j++) {
        ulonglong2 w;
        w.x = cacc[2 * j]; w.y = cacc[2 * j + 1];
        *(ulonglong2*)(pb + j * 128 + lane * 4) = w;
    }
    if (lane == 0) { pb[H] = m; pb[H + 1] = s; }
}

// ---------------------------------------------------------------------------
// Combine partials — MLP-oriented (R12, known good).
// ---------------------------------------------------------------------------
__global__ void __launch_bounds__(256)
combine_kernel(const float* __restrict__ prior,
               float* __restrict__ out, int write_attn)
{
    int b  = blockIdx.x;
    int sl = blockIdx.y;
    int t  = threadIdx.x;
    int c4 = t & 63;
    int g  = t >> 6;

    __shared__ float  shm[CHUNKS], shs[CHUNKS], shw[CHUNKS];
    __shared__ float  shM, shS;
    __shared__ float4 red[4][64];

    if (t < CHUNKS) {
        shm[t] = g_part[(size_t)(b * CHUNKS + t) * PS + H];
        shs[t] = g_part[(size_t)(b * CHUNKS + t) * PS + H + 1];
    }
    __syncthreads();
    if (t < 32) {
        float M = shm[t];
        #pragma unroll
        for (int off = 16; off > 0; off >>= 1)
            M = fmaxf(M, __shfl_xor_sync(0xffffffffu, M, off));
        float w = expf(shm[t] - M);
        float S = shs[t] * w;
        #pragma unroll
        for (int off = 16; off > 0; off >>= 1)
            S += __shfl_xor_sync(0xffffffffu, S, off);
        shw[t] = w;
        if (t == 0) { shM = M; shS = S; }
    }
    __syncthreads();
    float M = shM;
    float invS = 1.0f / shS;

    {
        int h = sl * 256 + c4 * 4;
        const float* pp = g_part + (size_t)b * CHUNKS * PS + h;
        float4 acc = make_float4(0.f, 0.f, 0.f, 0.f);
        #pragma unroll
        for (int i = 0; i < 8; i++) {
            int ci = g * 8 + i;
            float4 v = *(const float4*)(pp + (size_t)ci * PS);
            float w = shw[ci];
            acc.x += w * v.x; acc.y += w * v.y;
            acc.z += w * v.z; acc.w += w * v.w;
        }
        red[g][c4] = acc;
    }
    __syncthreads();

    if (t < 64) {
        float4 a0 = red[0][t], a1 = red[1][t], a2 = red[2][t], a3 = red[3][t];
        float4 o;
        o.x = (a0.x + a1.x + a2.x + a3.x) * invS;
        o.y = (a0.y + a1.y + a2.y + a3.y) * invS;
        o.z = (a0.z + a1.z + a2.z + a3.z) * invS;
        o.w = (a0.w + a1.w + a2.w + a3.w) * invS;
        *(float4*)(g_cat + (size_t)b * H2 + H + sl * 256 + t * 4) = o;
    }

    if (write_attn) {
        size_t base = (size_t)B * V + (size_t)B * H + (size_t)b * L;
        int l0 = sl * (L / 4);
        for (int l = l0 + t; l < l0 + L / 4; l += 256)
            out[base + l] = expf(g_energy[(size_t)b * L + l] - M) * invS;
    }

    if (sl == 0 && t < P)
        g_catp[(size_t)b * KO + H + t] = prior[(size_t)b * P + t];
}

// ---------------------------------------------------------------------------
// fp16 mma.sync GEMM core (m16n8k16)
// ---------------------------------------------------------------------------
#define OKT 32
#define HSTRIDE 20          // half2 per row

__device__ __forceinline__ void mma_f16(float* d, uint32_t a0, uint32_t a1,
                                        uint32_t a2, uint32_t a3,
                                        uint32_t b0, uint32_t b1)
{
    asm volatile(
        "mma.sync.aligned.m16n8k16.row.col.f32.f16.f16.f32 "
        "{%0,%1,%2,%3}, {%4,%5,%6,%7}, {%8,%9}, {%0,%1,%2,%3};"
        : "+f"(d[0]), "+f"(d[1]), "+f"(d[2]), "+f"(d[3])
        : "r"(a0), "r"(a1), "r"(a2), "r"(a3), "r"(b0), "r"(b1));
}

// ---------------------------------------------------------------------------
// Output GEMM (R12 known-good)
// ---------------------------------------------------------------------------
#define OTILES (KO / OKT)   // 36

__global__ void __launch_bounds__(256, 2)
out_gemm_tc_kernel(const float* __restrict__ Wout,
                   const float* __restrict__ bout,
                   float* __restrict__ outp)
{
    __shared__ uint32_t A_h[2][128 * HSTRIDE];
    __shared__ uint32_t B_h[2][64 * HSTRIDE];

    int tid   = threadIdx.x;
    int wid   = tid >> 5;
    int lane  = tid & 31;
    int gid   = lane >> 2;
    int tig   = lane & 3;
    int vbase = blockIdx.x * 128;

    int warp_m = wid & 1;
    int warp_n = wid >> 1;
    int mbase  = warp_m * 64;
    int nbase  = warp_n * 16;

    int arow = tid >> 3;
    int ac4  = tid & 7;

    float acc[4][2][4];
    #pragma unroll
    for (int mt = 0; mt < 4; mt++)
        #pragma unroll
        for (int nt = 0; nt < 2; nt++)
            #pragma unroll
            for (int i = 0; i < 4; i++) acc[mt][nt][i] = 0.0f;

    float4 pa[4], pb[2];

    #pragma unroll
    for (int j = 0; j < 4; j++) {
        int row = arow + j * 32;
        pa[j] = *(const float4*)(Wout + (size_t)(vbase + row) * KO + ac4 * 4);
    }
    #pragma unroll
    for (int j = 0; j < 2; j++) {
        int row = arow + j * 32;
        pb[j] = *(const float4*)(g_catp + (size_t)row * KO + ac4 * 4);
    }
    #pragma unroll
    for (int j = 0; j < 4; j++) {
        int row = arow + j * 32;
        *(uint2*)&A_h[0][row * HSTRIDE + ac4 * 2] =
            make_uint2(f2h2(pa[j].x, pa[j].y), f2h2(pa[j].z, pa[j].w));
    }
    #pragma unroll
    for (int j = 0; j < 2; j++) {
        int row = arow + j * 32;
        *(uint2*)&B_h[0][row * HSTRIDE + ac4 * 2] =
            make_uint2(f2h2(pb[j].x, pb[j].y), f2h2(pb[j].z, pb[j].w));
    }

    #pragma unroll 1
    for (int t = 0; t < OTILES; t++) {
        __syncthreads();
        int buf = t & 1;

        if (t + 1 < OTILES) {
            int kt = (t + 1) * OKT;
            #pragma unroll
            for (int j = 0; j < 4; j++) {
                int row = arow + j * 32;
                pa[j] = *(const float4*)(Wout + (size_t)(vbase + row) * KO + kt + ac4 * 4);
            }
            #pragma unroll
            for (int j = 0; j < 2; j++) {
                int row = arow + j * 32;
                pb[j] = *(const float4*)(g_catp + (size_t)row * KO + kt + ac4 * 4);
            }
        }

        #pragma unroll
        for (int kb = 0; kb < 2; kb++) {
            int k2 = kb * 8 + tig;

            uint32_t bf0[2], bf1[2];
            #pragma unroll
            for (int nt = 0; nt < 2; nt++) {
                int n0 = nbase + nt * 8 + gid;
                bf0[nt] = B_h[buf][n0 * HSTRIDE + k2];
                bf1[nt] = B_h[buf][n0 * HSTRIDE + k2 + 4];
            }
            #pragma unroll
            for (int mt = 0; mt < 4; mt++) {
                int r0 = mbase + mt * 16 + gid;
                uint32_t a0 = A_h[buf][r0 * HSTRIDE + k2];
                uint32_t a1 = A_h[buf][(r0 + 8) * HSTRIDE + k2];
                uint32_t a2 = A_h[buf][r0 * HSTRIDE + k2 + 4];
                uint32_t a3 = A_h[buf][(r0 + 8) * HSTRIDE + k2 + 4];
                mma_f16(acc[mt][0], a0, a1, a2, a3, bf0[0], bf1[0]);
                mma_f16(acc[mt][1], a0, a1, a2, a3, bf0[1], bf1[1]);
            }
        }

        if (t + 1 < OTILES) {
            int nbuf = buf ^ 1;
            #pragma unroll
            for (int j = 0; j < 4; j++) {
                int row = arow + j * 32;
                *(uint2*)&A_h[nbuf][row * HSTRIDE + ac4 * 2] =
                    make_uint2(f2h2(pa[j].x, pa[j].y), f2h2(pa[j].z, pa[j].w));
            }
            #pragma unroll
            for (int j = 0; j < 2; j++) {
                int row = arow + j * 32;
                *(uint2*)&B_h[nbuf][row * HSTRIDE + ac4 * 2] =
                    make_uint2(f2h2(pb[j].x, pb[j].y), f2h2(pb[j].z, pb[j].w));
            }
        }
    }

    #pragma unroll
    for (int mt = 0; mt < 4; mt++) {
        int v0 = vbase + mbase + mt * 16 + gid;
        float bias0 = bout[v0];
        float bias1 = bout[v0 + 8];
        #pragma unroll
        for (int nt = 0; nt < 2; nt++) {
            int bcol = nbase + nt * 8 + 2 * tig;
            outp[(size_t)bcol * V + v0]           = acc[mt][nt][0] + bias0;
            outp[(size_t)(bcol + 1) * V + v0]     = acc[mt][nt][1] + bias0;
            outp[(size_t)bcol * V + v0 + 8]       = acc[mt][nt][2] + bias1;
            outp[(size_t)(bcol + 1) * V + v0 + 8] = acc[mt][nt][3] + bias1;
        }
    }
}

// ---------------------------------------------------------------------------
// Concat GEMM via fp16 mma.sync (R14 known-good)
// ---------------------------------------------------------------------------
#define CTILES 4   // 128 / OKT

__global__ void __launch_bounds__(256, 2)
cgemm_tc_kernel(const float* __restrict__ Wc)
{
    __shared__ uint32_t A_h[2][128 * HSTRIDE];
    __shared__ uint32_t B_h[2][64 * HSTRIDE];

    int tid   = threadIdx.x;
    int wid   = tid >> 5;
    int lane  = tid & 31;
    int gid   = lane >> 2;
    int tig   = lane & 3;
    int vbase = blockIdx.x * 128;
    int k0    = blockIdx.y * 128;
    int yoff  = blockIdx.y * 64;

    int warp_m = wid & 1;
    int warp_n = wid >> 1;
    int mbase  = warp_m * 64;
    int nbase  = warp_n * 16;

    int arow = tid >> 3;
    int ac4  = tid & 7;

    float acc[4][2][4];
    #pragma unroll
    for (int mt = 0; mt < 4; mt++)
        #pragma unroll
        for (int nt = 0; nt < 2; nt++)
            #pragma unroll
            for (int i = 0; i < 4; i++) acc[mt][nt][i] = 0.0f;

    float4 pa[4], pb[2];

    #pragma unroll
    for (int j = 0; j < 4; j++) {
        int row = arow + j * 32;
        pa[j] = *(const float4*)(Wc + (size_t)(vbase + row) * H2 + k0 + ac4 * 4);
    }
    #pragma unroll
    for (int j = 0; j < 2; j++) {
        int row = arow + j * 32;
        pb[j] = *(const float4*)(g_cat + (size_t)row * H2 + k0 + ac4 * 4);
    }
    #pragma unroll
    for (int j = 0; j < 4; j++) {
        int row = arow + j * 32;
        *(uint2*)&A_h[0][row * HSTRIDE + ac4 * 2] =
            make_uint2(f2h2(pa[j].x, pa[j].y), f2h2(pa[j].z, pa[j].w));
    }
    #pragma unroll
    for (int j = 0; j < 2; j++) {
        int row = arow + j * 32;
        *(uint2*)&B_h[0][row * HSTRIDE + ac4 * 2] =
            make_uint2(f2h2(pb[j].x, pb[j].y), f2h2(pb[j].z, pb[j].w));
    }

    #pragma unroll 1
    for (int t = 0; t < CTILES; t++) {
        __syncthreads();
        int buf = t & 1;

        if (t + 1 < CTILES) {
            int kt = k0 + (t + 1) * OKT;
            #pragma unroll
            for (int j = 0; j < 4; j++) {
                int row = arow + j * 32;
                pa[j] = *(const float4*)(Wc + (size_t)(vbase + row) * H2 + kt + ac4 * 4);
            }
            #pragma unroll
            for (int j = 0; j < 2; j++) {
                int row = arow + j * 32;
                pb[j] = *(const float4*)(g_cat + (size_t)row * H2 + kt + ac4 * 4);
            }
        }

        #pragma unroll
        for (int kb = 0; kb < 2; kb++) {
            int k2 = kb * 8 + tig;

            uint32_t bf0[2], bf1[2];
            #pragma unroll
            for (int nt = 0; nt < 2; nt++) {
                int n0 = nbase + nt * 8 + gid;
                bf0[nt] = B_h[buf][n0 * HSTRIDE + k2];
                bf1[nt] = B_h[buf][n0 * HSTRIDE + k2 + 4];
            }
            #pragma unroll
            for (int mt = 0; mt < 4; mt++) {
                int r0 = mbase + mt * 16 + gid;
                uint32_t a0 = A_h[buf][r0 * HSTRIDE + k2];
                uint32_t a1 = A_h[buf][(r0 + 8) * HSTRIDE + k2];
                uint32_t a2 = A_h[buf][r0 * HSTRIDE + k2 + 4];
                uint32_t a3 = A_h[buf][(r0 + 8) * HSTRIDE + k2 + 4];
                mma_f16(acc[mt][0], a0, a1, a2, a3, bf0[0], bf1[0]);
                mma_f16(acc[mt][1], a0, a1, a2, a3, bf0[1], bf1[1]);
            }
        }

        if (t + 1 < CTILES) {
            int nbuf = buf ^ 1;
            #pragma unroll
            for (int j = 0; j < 4; j++) {
                int row = arow + j * 32;
                *(uint2*)&A_h[nbuf][row * HSTRIDE + ac4 * 2] =
                    make_uint2(f2h2(pa[j].x, pa[j].y), f2h2(pa[j].z, pa[j].w));
            }
            #pragma unroll
            for (int j = 0; j < 2; j++) {
                int row = arow + j * 32;
                *(uint2*)&B_h[nbuf][row * HSTRIDE + ac4 * 2] =
                    make_uint2(f2h2(pb[j].x, pb[j].y), f2h2(pb[j].z, pb[j].w));
            }
        }
    }

    #pragma unroll
    for (int mt = 0; mt < 4; mt++) {
        int n0 = vbase + mbase + mt * 16 + gid;
        #pragma unroll
        for (int nt = 0; nt < 2; nt++) {
            int bcol = nbase + nt * 8 + 2 * tig;
            g_pcc[(size_t)(yoff + bcol) * H + n0]           = acc[mt][nt][0];
            g_pcc[(size_t)(yoff + bcol + 1) * H + n0]       = acc[mt][nt][1];
            g_pcc[(size_t)(yoff + bcol) * H + n0 + 8]       = acc[mt][nt][2];
            g_pcc[(size_t)(yoff + bcol + 1) * H + n0 + 8]   = acc[mt][nt][3];
        }
    }
}

// ---------------------------------------------------------------------------
extern "C" void kernel_launch(void* const* d_in, const int* in_sizes, int n_in,
                              void* d_out, int out_size)
{
    const int*   seq   = (const int*)d_in[0];   // int32 (JAX x64 disabled)
    const float* lh    = (const float*)d_in[1];
    const float* enc   = (const float*)d_in[2];
    const float* prior = (const float*)d_in[3];
    const float* emb   = (const float*)d_in[4];
    const float* Wih   = (const float*)d_in[5];
    const float* Whh   = (const float*)d_in[6];
    const float* bih   = (const float*)d_in[7];
    const float* bhh   = (const float*)d_in[8];
    const float* Wc    = (const float*)d_in[9];
    const float* bc    = (const float*)d_in[10];
    const float* Wout  = (const float*)d_in[11];
    const float* bout  = (const float*)d_in[12];

    float* out = (float*)d_out;
    long long need_h    = (long long)B * V + (long long)B * H;
    long long need_attn = need_h + (long long)B * L;
    float* out_h = ((long long)out_size >= need_h) ? out + (size_t)B * V : nullptr;
    int write_attn = ((long long)out_size >= need_attn) ? 1 : 0;

    float* pih; cudaGetSymbolAddress((void**)&pih, g_pih);
    float* phh; cudaGetSymbolAddress((void**)&phh, g_phh);

    cudaFuncSetAttribute(attn1_kernel,
                         cudaFuncAttributeMaxDynamicSharedMemorySize, 65536);

    // 1. GRU GEMMs (fp32 SIMT — h_new must stay exact), ksplit=8:
    gemm_kernel<<<dim3(3 * H / 128, KSPL, 2), 256>>>(
        emb, lh, Wih, Whh, pih, phh, nullptr, 3 * H, H, KSPL, 3 * H, seq);

    // 2. gates -> h_new (vectorized)
    gru_gates_kernel<<<B * H / 4 / 256, 256>>>(lh, bih, bhh, out_h);

    // 3. flash attention over encoder_outputs (read once, 2-stage cp.async)
    attn1_kernel<<<B * CHUNKS / 4, 128, 65536>>>(enc);

    // 4. combine -> context, attn weights, prior copy
    combine_kernel<<<dim3(B, 4), 256>>>(prior, out, write_attn);

    // 5. concat GEMM via fp16 tensor cores (ksplit=16) + reduce/tanh
    cgemm_tc_kernel<<<dim3(H / 128, 16), 256>>>(Wc);
    creduce_kernel<<<B * H / 4 / 256, 256>>>(bc);

    // 6. output GEMM (N=32000, K=1152) via mma.sync fp16 (R12 config)
    out_gemm_tc_kernel<<<V / 128, 256>>>(Wout, bout, out);
}